// round 15
// baseline (speedup 1.0000x reference)
#include <cuda_runtime.h>
#include <math.h>
#include <stdint.h>

#define NG   256
#define NG3  16777216
#define NW   (NG3/32)           // 524288 bit-words per mask
#define SP   0.390625f          // 100/256, exact in f32

// combined grid: per z-word, lo32 = occ bits, hi32 = prot bits
// zero-initialized at module load; blur kernel re-zeroes it each call.
static __device__ unsigned long long g_bits[NW];
static __device__ uint32_t           g_solvb[NW];

// smallest float T with (s < T) <=> (sqrt_rn(s) < R)
__device__ __forceinline__ float cut_threshold(float R) {
    float t = __fmul_rn(R, R);
    while (__fsqrt_rn(t) >= R)
        t = __uint_as_float(__float_as_uint(t) - 1u);
    while (__fsqrt_rn(__uint_as_float(__float_as_uint(t) + 1u)) < R)
        t = __uint_as_float(__float_as_uint(t) + 1u);
    return __uint_as_float(__float_as_uint(t) + 1u);
}

// exact reference predicate: fadd(rxy2, fmul(rz,rz)) < T, rz single-rounded
__device__ __forceinline__ bool cell_pass(int zc, float az, float rxy2, float T) {
    float rz = __fmaf_rn((float)zc, SP, -az);   // zc*SP exact => == fsub(fmul)
    float s  = __fadd_rn(rxy2, __fmul_rn(rz, rz));
    return s < T;
}

// contiguous passing z-interval [lo,hi] for threshold T (given rxy2 < T)
__device__ __forceinline__ void chord_bounds(float az, float rxy2, float T,
                                             int& lo, int& hi) {
    float t = __fsub_rn(T, rxy2);               // >= 0
    float h = __fsqrt_rn(t);
    int zl0 = __float2int_ru(__fmaf_rn(az - h, 2.56f, -1.25e-4f));
    int zh0 = __float2int_rd(__fmaf_rn(az + h, 2.56f,  1.25e-4f));
    lo = cell_pass(zl0, az, rxy2, T) ? zl0 : zl0 + 1;
    hi = cell_pass(zh0, az, rxy2, T) ? zh0 : zh0 - 1;
}

// ---- splat: 4 atoms/block; per-atom scalars computed once by 8 lanes ----
__global__ void splat_kernel(const float* __restrict__ xyz,
                             const float* __restrict__ vdw,
                             int n_atoms) {
    __shared__ float sAx[4], sAy[4], sAz[4], sTocc[4], sTpro[4];
    __shared__ int   sBx[4], sBy[4], sBz[4];
    int blk = blockIdx.x;
    int tid = threadIdx.x;

    if (tid < 8) {                         // 8 cut_threshold calls, one per lane
        int k = tid >> 1;
        int a = blk * 4 + k;
        if (a < n_atoms) {
            float vr = vdw[a];
            float R  = (tid & 1) ? vr : __fadd_rn(vr, 1.1f);
            float T  = cut_threshold(R);
            if (tid & 1) sTpro[k] = T; else sTocc[k] = T;
        }
    }
    if (tid < 4) {                         // base cell + position, once per atom
        int a = blk * 4 + tid;
        if (a < n_atoms) {
            float ax = xyz[3*a], ay = xyz[3*a+1], az = xyz[3*a+2];
            sAx[tid] = ax; sAy[tid] = ay; sAz[tid] = az;
            sBx[tid] = (int)floorf(__fdiv_rn(ax, SP));
            sBy[tid] = (int)floorf(__fdiv_rn(ay, SP));
            sBz[tid] = (int)floorf(__fdiv_rn(az, SP));
        }
    }
    __syncthreads();

    int k = tid >> 6;
    int a = blk * 4 + k;
    if (a >= n_atoms) return;
    int lane = tid & 63;
    float ax = sAx[k], ay = sAy[k], az = sAz[k];
    float Tocc = sTocc[k], Tpro = sTpro[k];
    int bx = sBx[k], by = sBy[k], bz = sBz[k];
    int zs = bz - 8;
    int s0 = zs & 255;
    int w0 = s0 >> 5, off = s0 & 31;

    #pragma unroll
    for (int it = 0; it < 5; ++it) {
        int p = lane + it * 64;
        // iterations 0..3: p <= 255 < 289 always (lane <= 63)
        if (it < 4 || p < 289) {
            int dx = p / 17 - 8;
            int dy = p % 17 - 8;
            int cx = bx + dx, cy = by + dy;
            // (cx*SP) exact in f32 => FMA == reference fsub(fmul(cx,SP), ax)
            float rx = __fmaf_rn((float)cx, SP, -ax);
            float ry = __fmaf_rn((float)cy, SP, -ay);
            float rxy2 = __fadd_rn(__fmul_rn(rx, rx), __fmul_rn(ry, ry));
            if (rxy2 < Tocc) {                    // exact cull (s >= rxy2)
                int lo, hi;
                chord_bounds(az, rxy2, Tocc, lo, hi);
                lo = max(lo, bz - 8);
                hi = min(hi, bz + 8);             // reference window truncation
                if (hi >= lo) {
                    unsigned mO = (2u << (hi - zs)) - (1u << (lo - zs));
                    unsigned mP = 0;
                    if (rxy2 < Tpro) {
                        int pl, ph;
                        chord_bounds(az, rxy2, Tpro, pl, ph);
                        pl = max(pl, bz - 8);
                        ph = min(ph, bz + 8);
                        if (ph >= pl) mP = (2u << (ph - zs)) - (1u << (pl - zs));
                    }
                    unsigned long long osh = ((unsigned long long)mO) << off;
                    unsigned long long psh = ((unsigned long long)mP) << off;
                    int colbase = ((cx & 255) << 8) | (cy & 255);
                    unsigned long long v0 = ((unsigned long long)(unsigned)psh << 32)
                                          |  (unsigned long long)(unsigned)osh;
                    unsigned long long v1 = ((unsigned long long)(unsigned)(psh >> 32) << 32)
                                          |  (unsigned long long)(unsigned)(osh >> 32);
                    if (v0) atomicOr(&g_bits[(w0 << 16) + colbase], v0);
                    if (v1) atomicOr(&g_bits[((((w0 + 1) & 7)) << 16) + colbase], v1);
                }
            }
        }
    }
}

// ---- classify: solv = ds | (nb & ~prot); coalesced (fast index -> gy) ----
__global__ void classify_kernel() {
    __shared__ uint32_t sD0[8 * 400];
    __shared__ uint32_t sD1[8 * 400];
    __shared__ uint32_t sD2[8 * 400];
    int bx0 = (blockIdx.x & 15) * 16;
    int by0 = (blockIdx.x >> 4) * 16;
    int t = threadIdx.x;

    for (int c = t; c < 400; c += 256) {
        int iy = c % 20, ix = c / 20;              // iy fast -> gy contiguous
        int gx = (bx0 + ix - 2) & 255;
        int gy = (by0 + iy - 2) & 255;
        int col = (gx << 8) | gy;
        uint32_t ds[8], d1[8], d2[8];
        #pragma unroll
        for (int i = 0; i < 8; i++)
            ds[i] = ~(uint32_t)g_bits[(i << 16) + col];
        #pragma unroll
        for (int i = 0; i < 8; i++)
            d1[i] = ds[i] | (ds[i] << 1) | (ds[(i+7)&7] >> 31)
                          | (ds[i] >> 1) | (ds[(i+1)&7] << 31);
        #pragma unroll
        for (int i = 0; i < 8; i++)
            d2[i] = d1[i] | (d1[i] << 1) | (d1[(i+7)&7] >> 31)
                          | (d1[i] >> 1) | (d1[(i+1)&7] << 31);
        #pragma unroll
        for (int i = 0; i < 8; i++) {
            sD0[i*400 + c] = ds[i];
            sD1[i*400 + c] = d1[i];
            sD2[i*400 + c] = d2[i];
        }
    }
    __syncthreads();

    int iy = (t & 15) + 2, ix = (t >> 4) + 2;      // iy fast -> gy contiguous
    int gx = (bx0 + ix - 2) & 255;
    int gy = (by0 + iy - 2) & 255;
    int col = (gx << 8) | gy;
    int cc = ix * 20 + iy;
    #pragma unroll
    for (int i = 0; i < 8; i++) {
        const uint32_t* D0 = sD0 + i * 400;
        const uint32_t* D1 = sD1 + i * 400;
        const uint32_t* D2 = sD2 + i * 400;
        uint32_t nb =
            D2[cc] | D2[cc+1]  | D2[cc-1]  | D2[cc+20] | D2[cc-20] |
            D1[cc+21] | D1[cc+19] | D1[cc-19] | D1[cc-21] |
            D1[cc+2]  | D1[cc-2]  | D1[cc+40] | D1[cc-40] |
            D0[cc+22] | D0[cc+18] | D0[cc-18] | D0[cc-22] |
            D0[cc+41] | D0[cc+39] | D0[cc-39] | D0[cc-41];
        uint32_t p = (uint32_t)(g_bits[(i << 16) + col] >> 32);
        g_solvb[(i << 16) + col] = D0[cc] | (nb & ~p);
    }
}

// CSA of 4 one-bit vectors: sum = lo + 2*mid + 4*hi
__device__ __forceinline__ void csa4(uint32_t a, uint32_t b, uint32_t c, uint32_t d,
                                     uint32_t& lo, uint32_t& mid, uint32_t& hi) {
    uint32_t s1 = a ^ b ^ c;
    uint32_t m1 = (a & b) | (c & (a | b));
    uint32_t cy = s1 & d;
    lo  = s1 ^ d;
    mid = m1 ^ cy;
    hi  = m1 & cy;
}

// ---- fused 27-tap blur v8: packed-byte registers + lazy LUT + 2-phase out ----
// Same arithmetic as v7 (bit-identical); restructured for <=36 regs + 23KB smem.
__global__ __launch_bounds__(256, 7)
void blur_fused8_kernel(float4* __restrict__ out,
                        float a0, float a1,
                        float p00, float p01, float p11) {
    __shared__ uint32_t sB[8][3][40];     // interior at [4+i], halos [3] and [36]
    __shared__ float    sLut[128];
    __shared__ float    sHi[8][32];
    __shared__ float    sLo[8][32];
    __shared__ float4   sOutH[1024];      // half-size transpose buffer

    int t  = threadIdx.x;
    int x  = blockIdx.x >> 3;
    int y0 = (blockIdx.x & 7) << 5;

    // re-zero splat grid for the next kernel_launch call
    g_bits[blockIdx.x * 256 + t] = 0ULL;

    if (t < 128) {
        float fE = (float)( t       & 7);
        float fC = (float)((t >> 3) & 1);
        float fK = (float)((t >> 4) & 7);
        sLut[t] = fmaf(p00, fC, fmaf(p01, fE, p11 * fK));
    }
    if (t < 192) {                         // interior: 24 (w,xi) x 8 uint4
        int combo = t >> 3;                // 0..23
        int q     = t & 7;                 // 0..7
        int w  = combo / 3;
        int xi = combo % 3;
        int gx = (x + xi - 1) & 255;
        const uint4* src = reinterpret_cast<const uint4*>(
            &g_solvb[(w << 16) | (gx << 8) | y0]);
        *reinterpret_cast<uint4*>(&sB[w][xi][4 + (q << 2)]) = src[q];
    } else if (t < 240) {                  // halos: 24 combos x 2 sides
        int e = t - 192;
        int combo = e >> 1;
        int side  = e & 1;
        int w  = combo / 3;
        int xi = combo % 3;
        int gx = (x + xi - 1) & 255;
        int gy = side ? ((y0 + 32) & 255) : ((y0 - 1) & 255);
        sB[w][xi][side ? 36 : 3] = g_solvb[(w << 16) | (gx << 8) | gy];
    }
    __syncthreads();

    int yl = t & 31;          // lane = y
    int w  = t >> 5;          // warp = word

    uint32_t cc = sB[w][1][4+yl];
    uint32_t ea = sB[w][0][4+yl], eb = sB[w][2][4+yl];
    uint32_t ec = sB[w][1][3+yl], ed = sB[w][1][5+yl];
    uint32_t ka = sB[w][0][3+yl], kb = sB[w][2][3+yl];
    uint32_t kc = sB[w][0][5+yl], kd = sB[w][2][5+yl];

    uint32_t E0, E1, E2, K0, K1, K2;
    csa4(ea, eb, ec, ed, E0, E1, E2);
    csa4(ka, kb, kc, kd, K0, K1, K2);

    // pk[q] holds cells z=4q..4q+3 as bytes (byte = E + 8C + 16K, <= 76)
    uint32_t pk[8];
    #pragma unroll
    for (int G = 0; G < 4; G++) {
        uint32_t sel = (uint32_t)G | ((uint32_t)(4 + G) << 4);
        uint32_t t01 = __byte_perm(E0, E1, sel);
        uint32_t t23 = __byte_perm(E2, cc, sel);
        uint32_t t45 = __byte_perm(K0, K1, sel);
        uint32_t t67 = __byte_perm(K2, 0u, sel);
        uint32_t lo  = __byte_perm(t01, t23, 0x5410);
        uint32_t hi  = __byte_perm(t45, t67, 0x5410);
        unsigned long long xb = (unsigned long long)lo
                              | ((unsigned long long)hi << 32);
        unsigned long long yb;
        yb = (xb ^ (xb >> 7))  & 0x00AA00AA00AA00AAULL; xb ^= yb ^ (yb << 7);
        yb = (xb ^ (xb >> 14)) & 0x0000CCCC0000CCCCULL; xb ^= yb ^ (yb << 14);
        yb = (xb ^ (xb >> 28)) & 0x00000000F0F0F0F0ULL; xb ^= yb ^ (yb << 28);
        pk[2*G]   = (uint32_t)xb;
        pk[2*G+1] = (uint32_t)(xb >> 32);
    }

    #define LUTB(q, b) sLut[(pk[q] >> (8*(b))) & 0xFFu]

    // word halos via smem (neighbor word lives in another warp)
    sLo[w][yl] = LUTB(0, 0);               // g at z=0
    sHi[w][yl] = sLut[pk[7] >> 24];        // g at z=31
    __syncthreads();
    float hzm = sHi[(w + 7) & 7][yl];      // g at z=-1
    float hzp = sLo[(w + 1) & 7][yl];      // g at z=32

    // rolling 6-value window: c0 = g(4k-1), c1..c4 = g(4k..4k+3), c5 = g(4k+4)
    float c0 = hzm;
    float c1 = LUTB(0,0), c2 = LUTB(0,1), c3 = LUTB(0,2), c4 = LUTB(0,3);

    // phase A: k = 0..3
    #pragma unroll
    for (int k = 0; k < 4; k++) {
        float c5 = LUTB(k+1, 0);
        float4 o;
        o.x = fmaf(a0, c1, a1 * (c0 + c2));
        o.y = fmaf(a0, c2, a1 * (c1 + c3));
        o.z = fmaf(a0, c3, a1 * (c2 + c4));
        o.w = fmaf(a0, c4, a1 * (c3 + c5));
        sOutH[(yl << 5) + (((w << 2) + k) ^ yl)] = o;
        c0 = c4; c1 = c5;
        c2 = LUTB(k+1, 1); c3 = LUTB(k+1, 2); c4 = LUTB(k+1, 3);
    }
    __syncthreads();
    #pragma unroll
    for (int i = 0; i < 4; i++) {
        int flat = i * 256 + t;
        int yy = flat >> 5, zq = flat & 31;
        float4 v = sOutH[(yy << 5) + (zq ^ yy)];
        int zg = ((zq >> 2) << 3) + (zq & 3);
        out[(x << 14) | ((y0 + yy) << 6) | zg] = v;
    }
    __syncthreads();

    // phase B: k = 4..7 (window carried across the barrier in registers)
    #pragma unroll
    for (int k = 4; k < 8; k++) {
        float c5 = (k == 7) ? hzp : LUTB(k+1, 0);
        float4 o;
        o.x = fmaf(a0, c1, a1 * (c0 + c2));
        o.y = fmaf(a0, c2, a1 * (c1 + c3));
        o.z = fmaf(a0, c3, a1 * (c2 + c4));
        o.w = fmaf(a0, c4, a1 * (c3 + c5));
        sOutH[(yl << 5) + (((w << 2) + (k - 4)) ^ yl)] = o;
        if (k < 7) {
            c0 = c4; c1 = c5;
            c2 = LUTB(k+1, 1); c3 = LUTB(k+1, 2); c4 = LUTB(k+1, 3);
        }
    }
    __syncthreads();
    #pragma unroll
    for (int i = 0; i < 4; i++) {
        int flat = i * 256 + t;
        int yy = flat >> 5, zq = flat & 31;
        float4 v = sOutH[(yy << 5) + (zq ^ yy)];
        int zg = ((zq >> 2) << 3) + (zq & 3) + 4;
        out[(x << 14) | ((y0 + yy) << 6) | zg] = v;
    }
    #undef LUTB
}

extern "C" void kernel_launch(void* const* d_in, const int* in_sizes, int n_in,
                              void* d_out, int out_size) {
    const float* xyz = (const float*)d_in[0];
    const float* vdw = (const float*)d_in[1];
    int n_atoms = in_sizes[1];

    // all double math on the HOST; device sees only f32
    double sigma = 1.1 / (100.0 / 256.0) / 4.0;
    double w = exp(-1.0 / (2.0 * sigma * sigma));
    double s = 1.0 + 2.0 * w;
    double a0d = 1.0 / s, a1d = w / s;
    float a0  = (float)a0d;
    float a1  = (float)a1d;
    float p00 = (float)(a0d * a0d);
    float p01 = (float)(a0d * a1d);
    float p11 = (float)(a1d * a1d);

    splat_kernel      <<<(n_atoms + 3) / 4, 256>>>(xyz, vdw, n_atoms);
    classify_kernel   <<<256, 256>>>();
    blur_fused8_kernel<<<2048, 256>>>((float4*)d_out, a0, a1, p00, p01, p11);
}

// round 16
// speedup vs baseline: 1.0511x; 1.0511x over previous
#include <cuda_runtime.h>
#include <math.h>
#include <stdint.h>

#define NG   256
#define NG3  16777216
#define NW   (NG3/32)           // 524288 bit-words per mask
#define SP   0.390625f          // 100/256, exact in f32

// combined grid: per z-word, lo32 = occ bits, hi32 = prot bits
// zero-initialized at module load; blur kernel re-zeroes it each call.
static __device__ unsigned long long g_bits[NW];
static __device__ uint32_t           g_solvb[NW];

// smallest float T with (s < T) <=> (sqrt_rn(s) < R)
__device__ __forceinline__ float cut_threshold(float R) {
    float t = __fmul_rn(R, R);
    while (__fsqrt_rn(t) >= R)
        t = __uint_as_float(__float_as_uint(t) - 1u);
    while (__fsqrt_rn(__uint_as_float(__float_as_uint(t) + 1u)) < R)
        t = __uint_as_float(__float_as_uint(t) + 1u);
    return __uint_as_float(__float_as_uint(t) + 1u);
}

// exact reference predicate: fadd(rxy2, fmul(rz,rz)) < T, rz single-rounded
__device__ __forceinline__ bool cell_pass(int zc, float az, float rxy2, float T) {
    float rz = __fmaf_rn((float)zc, SP, -az);   // zc*SP exact => == fsub(fmul)
    float s  = __fadd_rn(rxy2, __fmul_rn(rz, rz));
    return s < T;
}

// contiguous passing z-interval [lo,hi] for threshold T (given rxy2 < T)
__device__ __forceinline__ void chord_bounds(float az, float rxy2, float T,
                                             int& lo, int& hi) {
    float t = __fsub_rn(T, rxy2);               // >= 0
    float h = __fsqrt_rn(t);
    int zl0 = __float2int_ru(__fmaf_rn(az - h, 2.56f, -1.25e-4f));
    int zh0 = __float2int_rd(__fmaf_rn(az + h, 2.56f,  1.25e-4f));
    lo = cell_pass(zl0, az, rxy2, T) ? zl0 : zl0 + 1;
    hi = cell_pass(zh0, az, rxy2, T) ? zh0 : zh0 - 1;
}

// ---- splat: 4 atoms/block, 2 warps/atom, 16x16 window (4 iterations) ----
// dx,dy = -8 can never pass: |rx| >= 8*SP - 6e-6 = 3.1250 > R_max < 3.0.
// So the effective window is [-7,+8]^2 = 256 cells; z window stays [-8,+8].
__global__ void splat_kernel(const float* __restrict__ xyz,
                             const float* __restrict__ vdw,
                             int n_atoms) {
    __shared__ float sAx[4], sAy[4], sAz[4], sTocc[4], sTpro[4];
    __shared__ int   sBx[4], sBy[4], sBz[4];
    int blk = blockIdx.x;
    int tid = threadIdx.x;

    if (tid < 8) {                         // 8 cut_threshold calls, one per lane
        int k = tid >> 1;
        int a = blk * 4 + k;
        if (a < n_atoms) {
            float vr = vdw[a];
            float R  = (tid & 1) ? vr : __fadd_rn(vr, 1.1f);
            float T  = cut_threshold(R);
            if (tid & 1) sTpro[k] = T; else sTocc[k] = T;
        }
    }
    if (tid < 4) {                         // base cell + position, once per atom
        int a = blk * 4 + tid;
        if (a < n_atoms) {
            float ax = xyz[3*a], ay = xyz[3*a+1], az = xyz[3*a+2];
            sAx[tid] = ax; sAy[tid] = ay; sAz[tid] = az;
            sBx[tid] = (int)floorf(__fdiv_rn(ax, SP));
            sBy[tid] = (int)floorf(__fdiv_rn(ay, SP));
            sBz[tid] = (int)floorf(__fdiv_rn(az, SP));
        }
    }
    __syncthreads();

    int k = tid >> 6;
    int a = blk * 4 + k;
    if (a >= n_atoms) return;
    int lane = tid & 63;
    float ax = sAx[k], ay = sAy[k], az = sAz[k];
    float Tocc = sTocc[k], Tpro = sTpro[k];
    int bx = sBx[k], by = sBy[k], bz = sBz[k];
    int zs = bz - 8;
    int s0 = zs & 255;
    int w0 = s0 >> 5, off = s0 & 31;

    #pragma unroll
    for (int it = 0; it < 4; ++it) {
        int p = lane + it * 64;                   // 0..255, all valid
        int dx = (p >> 4) - 7;
        int dy = (p & 15) - 7;
        int cx = bx + dx, cy = by + dy;
        // (cx*SP) exact in f32 => FMA == reference fsub(fmul(cx,SP), ax)
        float rx = __fmaf_rn((float)cx, SP, -ax);
        float ry = __fmaf_rn((float)cy, SP, -ay);
        float rxy2 = __fadd_rn(__fmul_rn(rx, rx), __fmul_rn(ry, ry));
        if (rxy2 < Tocc) {                        // exact cull (s >= rxy2)
            int lo, hi;
            chord_bounds(az, rxy2, Tocc, lo, hi);
            lo = max(lo, bz - 8);
            hi = min(hi, bz + 8);                 // reference window truncation
            if (hi >= lo) {
                unsigned mO = (2u << (hi - zs)) - (1u << (lo - zs));
                unsigned mP = 0;
                if (rxy2 < Tpro) {
                    int pl, ph;
                    chord_bounds(az, rxy2, Tpro, pl, ph);
                    pl = max(pl, bz - 8);
                    ph = min(ph, bz + 8);
                    if (ph >= pl) mP = (2u << (ph - zs)) - (1u << (pl - zs));
                }
                unsigned long long osh = ((unsigned long long)mO) << off;
                unsigned long long psh = ((unsigned long long)mP) << off;
                int colbase = ((cx & 255) << 8) | (cy & 255);
                unsigned long long v0 = ((unsigned long long)(unsigned)psh << 32)
                                      |  (unsigned long long)(unsigned)osh;
                unsigned long long v1 = ((unsigned long long)(unsigned)(psh >> 32) << 32)
                                      |  (unsigned long long)(unsigned)(osh >> 32);
                if (v0) atomicOr(&g_bits[(w0 << 16) + colbase], v0);
                if (v1) atomicOr(&g_bits[((((w0 + 1) & 7)) << 16) + colbase], v1);
            }
        }
    }
}

// ---- classify: solv = ds | (nb & ~prot); coalesced (fast index -> gy) ----
__global__ void classify_kernel() {
    __shared__ uint32_t sD0[8 * 400];
    __shared__ uint32_t sD1[8 * 400];
    __shared__ uint32_t sD2[8 * 400];
    int bx0 = (blockIdx.x & 15) * 16;
    int by0 = (blockIdx.x >> 4) * 16;
    int t = threadIdx.x;

    for (int c = t; c < 400; c += 256) {
        int iy = c % 20, ix = c / 20;              // iy fast -> gy contiguous
        int gx = (bx0 + ix - 2) & 255;
        int gy = (by0 + iy - 2) & 255;
        int col = (gx << 8) | gy;
        uint32_t ds[8], d1[8], d2[8];
        #pragma unroll
        for (int i = 0; i < 8; i++)
            ds[i] = ~(uint32_t)g_bits[(i << 16) + col];
        #pragma unroll
        for (int i = 0; i < 8; i++)
            d1[i] = ds[i] | (ds[i] << 1) | (ds[(i+7)&7] >> 31)
                          | (ds[i] >> 1) | (ds[(i+1)&7] << 31);
        #pragma unroll
        for (int i = 0; i < 8; i++)
            d2[i] = d1[i] | (d1[i] << 1) | (d1[(i+7)&7] >> 31)
                          | (d1[i] >> 1) | (d1[(i+1)&7] << 31);
        #pragma unroll
        for (int i = 0; i < 8; i++) {
            sD0[i*400 + c] = ds[i];
            sD1[i*400 + c] = d1[i];
            sD2[i*400 + c] = d2[i];
        }
    }
    __syncthreads();

    int iy = (t & 15) + 2, ix = (t >> 4) + 2;      // iy fast -> gy contiguous
    int gx = (bx0 + ix - 2) & 255;
    int gy = (by0 + iy - 2) & 255;
    int col = (gx << 8) | gy;
    int cc = ix * 20 + iy;
    #pragma unroll
    for (int i = 0; i < 8; i++) {
        const uint32_t* D0 = sD0 + i * 400;
        const uint32_t* D1 = sD1 + i * 400;
        const uint32_t* D2 = sD2 + i * 400;
        uint32_t nb =
            D2[cc] | D2[cc+1]  | D2[cc-1]  | D2[cc+20] | D2[cc-20] |
            D1[cc+21] | D1[cc+19] | D1[cc-19] | D1[cc-21] |
            D1[cc+2]  | D1[cc-2]  | D1[cc+40] | D1[cc-40] |
            D0[cc+22] | D0[cc+18] | D0[cc-18] | D0[cc-22] |
            D0[cc+41] | D0[cc+39] | D0[cc-39] | D0[cc-41];
        uint32_t p = (uint32_t)(g_bits[(i << 16) + col] >> 32);
        g_solvb[(i << 16) + col] = D0[cc] | (nb & ~p);
    }
}

// CSA of 4 one-bit vectors: sum = lo + 2*mid + 4*hi
__device__ __forceinline__ void csa4(uint32_t a, uint32_t b, uint32_t c, uint32_t d,
                                     uint32_t& lo, uint32_t& mid, uint32_t& hi) {
    uint32_t s1 = a ^ b ^ c;
    uint32_t m1 = (a & b) | (c & (a | b));
    uint32_t cy = s1 & d;
    lo  = s1 ^ d;
    mid = m1 ^ cy;
    hi  = m1 & cy;
}

// ---- fused 27-tap blur v7: per-cell 7-bit index -> 128-entry f32 LUT ----
__global__ __launch_bounds__(256)
void blur_fused7_kernel(float4* __restrict__ out,
                        float a0, float a1,
                        float p00, float p01, float p11) {
    __shared__ uint32_t sB[8][3][40];     // interior at [4+i], halos [3] and [36]
    __shared__ float    sLut[128];
    __shared__ float    sHi[8][32];
    __shared__ float    sLo[8][32];
    __shared__ float4   sOut[2048];

    int t  = threadIdx.x;
    int x  = blockIdx.x >> 3;
    int y0 = (blockIdx.x & 7) << 5;

    // re-zero splat grid for the next kernel_launch call
    g_bits[blockIdx.x * 256 + t] = 0ULL;

    if (t < 128) {
        float fE = (float)( t       & 7);
        float fC = (float)((t >> 3) & 1);
        float fK = (float)((t >> 4) & 7);
        sLut[t] = fmaf(p00, fC, fmaf(p01, fE, p11 * fK));
    }
    if (t < 192) {                         // interior: 24 (w,xi) x 8 uint4
        int combo = t >> 3;                // 0..23
        int q     = t & 7;                 // 0..7
        int w  = combo / 3;
        int xi = combo % 3;
        int gx = (x + xi - 1) & 255;
        const uint4* src = reinterpret_cast<const uint4*>(
            &g_solvb[(w << 16) | (gx << 8) | y0]);
        *reinterpret_cast<uint4*>(&sB[w][xi][4 + (q << 2)]) = src[q];
    } else if (t < 240) {                  // halos: 24 combos x 2 sides
        int e = t - 192;
        int combo = e >> 1;
        int side  = e & 1;
        int w  = combo / 3;
        int xi = combo % 3;
        int gx = (x + xi - 1) & 255;
        int gy = side ? ((y0 + 32) & 255) : ((y0 - 1) & 255);
        sB[w][xi][side ? 36 : 3] = g_solvb[(w << 16) | (gx << 8) | gy];
    }
    __syncthreads();

    int yl = t & 31;          // lane = y
    int w  = t >> 5;          // warp = word

    uint32_t cc = sB[w][1][4+yl];
    uint32_t ea = sB[w][0][4+yl], eb = sB[w][2][4+yl];
    uint32_t ec = sB[w][1][3+yl], ed = sB[w][1][5+yl];
    uint32_t ka = sB[w][0][3+yl], kb = sB[w][2][3+yl];
    uint32_t kc = sB[w][0][5+yl], kd = sB[w][2][5+yl];

    float gz[34];
    uint32_t E0, E1, E2, K0, K1, K2;
    csa4(ea, eb, ec, ed, E0, E1, E2);
    csa4(ka, kb, kc, kd, K0, K1, K2);
    #pragma unroll
    for (int G = 0; G < 4; G++) {
        uint32_t sel = (uint32_t)G | ((uint32_t)(4 + G) << 4);
        uint32_t t01 = __byte_perm(E0, E1, sel);
        uint32_t t23 = __byte_perm(E2, cc, sel);
        uint32_t t45 = __byte_perm(K0, K1, sel);
        uint32_t t67 = __byte_perm(K2, 0u, sel);
        uint32_t lo  = __byte_perm(t01, t23, 0x5410);
        uint32_t hi  = __byte_perm(t45, t67, 0x5410);
        unsigned long long xb = (unsigned long long)lo
                              | ((unsigned long long)hi << 32);
        unsigned long long yb;
        yb = (xb ^ (xb >> 7))  & 0x00AA00AA00AA00AAULL; xb ^= yb ^ (yb << 7);
        yb = (xb ^ (xb >> 14)) & 0x0000CCCC0000CCCCULL; xb ^= yb ^ (yb << 14);
        yb = (xb ^ (xb >> 28)) & 0x00000000F0F0F0F0ULL; xb ^= yb ^ (yb << 28);
        uint32_t blo = (uint32_t)xb, bhi = (uint32_t)(xb >> 32);
        float* g = &gz[1 + (G << 3)];
        g[0] = sLut[ blo        & 0xFFu];
        g[1] = sLut[(blo >>  8) & 0xFFu];
        g[2] = sLut[(blo >> 16) & 0xFFu];
        g[3] = sLut[ blo >> 24        ];
        g[4] = sLut[ bhi        & 0xFFu];
        g[5] = sLut[(bhi >>  8) & 0xFFu];
        g[6] = sLut[(bhi >> 16) & 0xFFu];
        g[7] = sLut[ bhi >> 24        ];
    }

    // word halos via smem (neighbor word lives in another warp)
    sLo[w][yl] = gz[1];
    sHi[w][yl] = gz[32];
    __syncthreads();
    gz[0]  = sHi[(w + 7) & 7][yl];
    gz[33] = sLo[(w + 1) & 7][yl];

    #pragma unroll
    for (int k = 0; k < 8; k++) {
        float4 o;
        o.x = fmaf(a0, gz[4*k+1], a1 * (gz[4*k+0] + gz[4*k+2]));
        o.y = fmaf(a0, gz[4*k+2], a1 * (gz[4*k+1] + gz[4*k+3]));
        o.z = fmaf(a0, gz[4*k+3], a1 * (gz[4*k+2] + gz[4*k+4]));
        o.w = fmaf(a0, gz[4*k+4], a1 * (gz[4*k+3] + gz[4*k+5]));
        sOut[(yl << 6) + (((w << 3) + k) ^ yl)] = o;
    }
    __syncthreads();

    #pragma unroll
    for (int k2 = 0; k2 < 8; k2++) {
        int flat = (k2 << 8) + t;
        int yy2 = flat >> 6;
        int zg2 = flat & 63;
        float4 v = sOut[(yy2 << 6) + (zg2 ^ yy2)];
        out[(x << 14) | ((y0 + yy2) << 6) | zg2] = v;
    }
}

extern "C" void kernel_launch(void* const* d_in, const int* in_sizes, int n_in,
                              void* d_out, int out_size) {
    const float* xyz = (const float*)d_in[0];
    const float* vdw = (const float*)d_in[1];
    int n_atoms = in_sizes[1];

    // all double math on the HOST; device sees only f32
    double sigma = 1.1 / (100.0 / 256.0) / 4.0;
    double w = exp(-1.0 / (2.0 * sigma * sigma));
    double s = 1.0 + 2.0 * w;
    double a0d = 1.0 / s, a1d = w / s;
    float a0  = (float)a0d;
    float a1  = (float)a1d;
    float p00 = (float)(a0d * a0d);
    float p01 = (float)(a0d * a1d);
    float p11 = (float)(a1d * a1d);

    splat_kernel      <<<(n_atoms + 3) / 4, 256>>>(xyz, vdw, n_atoms);
    classify_kernel   <<<256, 256>>>();
    blur_fused7_kernel<<<2048, 256>>>((float4*)d_out, a0, a1, p00, p01, p11);
}

// round 17
// speedup vs baseline: 1.0693x; 1.0173x over previous
#include <cuda_runtime.h>
#include <math.h>
#include <stdint.h>

#define NG   256
#define NG3  16777216
#define NW   (NG3/32)           // 524288 bit-words per mask
#define SP   0.390625f          // 100/256, exact in f32

// combined grid: per z-word, lo32 = occ bits, hi32 = prot bits
// zero-initialized at module load; blur kernel re-zeroes it each call.
static __device__ unsigned long long g_bits[NW];
static __device__ uint32_t           g_solvb[NW];

// smallest float T with (s < T) <=> (sqrt_rn(s) < R)
__device__ __forceinline__ float cut_threshold(float R) {
    float t = __fmul_rn(R, R);
    while (__fsqrt_rn(t) >= R)
        t = __uint_as_float(__float_as_uint(t) - 1u);
    while (__fsqrt_rn(__uint_as_float(__float_as_uint(t) + 1u)) < R)
        t = __uint_as_float(__float_as_uint(t) + 1u);
    return __uint_as_float(__float_as_uint(t) + 1u);
}

// exact reference predicate: fadd(rxy2, fmul(rz,rz)) < T, rz single-rounded
__device__ __forceinline__ bool cell_pass(int zc, float az, float rxy2, float T) {
    float rz = __fmaf_rn((float)zc, SP, -az);   // zc*SP exact => == fsub(fmul)
    float s  = __fadd_rn(rxy2, __fmul_rn(rz, rz));
    return s < T;
}

// contiguous passing z-interval [lo,hi] for threshold T (given rxy2 < T).
// approx sqrt is fine: estimate error <= ~5e-5 cells << guard 2e-4 << 1 cell;
// each boundary resolved by ONE exact predicate eval (est in {first-1, first}).
__device__ __forceinline__ void chord_bounds(float az, float rxy2, float T,
                                             float azm, float azp,
                                             int& lo, int& hi) {
    float t = __fsub_rn(T, rxy2);               // >= 0
    float h;
    asm("sqrt.approx.f32 %0, %1;" : "=f"(h) : "f"(t));
    int zl0 = __float2int_ru(__fmaf_rn(-h, 2.56f, azm));
    int zh0 = __float2int_rd(__fmaf_rn( h, 2.56f, azp));
    lo = cell_pass(zl0, az, rxy2, T) ? zl0 : zl0 + 1;
    hi = cell_pass(zh0, az, rxy2, T) ? zh0 : zh0 - 1;
}

// ---- splat: 4 atoms/block, 2 warps/atom, 16x16 window (4 iterations) ----
// dx,dy = -8 can never pass: |rx| >= 8*SP - 6e-6 > R_max < 3.0 -> window 16x16.
// z chords are naturally within [bz-7, bz+8] -> reference +-8 clamp never binds.
__global__ void splat_kernel(const float* __restrict__ xyz,
                             const float* __restrict__ vdw,
                             int n_atoms) {
    __shared__ float sAx[4], sAy[4], sAz[4], sTocc[4], sTpro[4];
    __shared__ float sAzm[4], sAzp[4];
    __shared__ int   sBx[4], sBy[4], sBz[4];
    int blk = blockIdx.x;
    int tid = threadIdx.x;

    if (tid < 8) {                         // 8 cut_threshold calls, one per lane
        int k = tid >> 1;
        int a = blk * 4 + k;
        if (a < n_atoms) {
            float vr = vdw[a];
            float R  = (tid & 1) ? vr : __fadd_rn(vr, 1.1f);
            float T  = cut_threshold(R);
            if (tid & 1) sTpro[k] = T; else sTocc[k] = T;
        }
    }
    if (tid < 4) {                         // base cell + position, once per atom
        int a = blk * 4 + tid;
        if (a < n_atoms) {
            float ax = xyz[3*a], ay = xyz[3*a+1], az = xyz[3*a+2];
            sAx[tid] = ax; sAy[tid] = ay; sAz[tid] = az;
            sAzm[tid] = __fmaf_rn(az, 2.56f, -2e-4f);
            sAzp[tid] = __fmaf_rn(az, 2.56f,  2e-4f);
            sBx[tid] = (int)floorf(__fdiv_rn(ax, SP));
            sBy[tid] = (int)floorf(__fdiv_rn(ay, SP));
            sBz[tid] = (int)floorf(__fdiv_rn(az, SP));
        }
    }
    __syncthreads();

    int k = tid >> 6;
    int a = blk * 4 + k;
    if (a >= n_atoms) return;
    int lane = tid & 63;
    float ax = sAx[k], ay = sAy[k], az = sAz[k];
    float azm = sAzm[k], azp = sAzp[k];
    float Tocc = sTocc[k], Tpro = sTpro[k];
    int bx = sBx[k], by = sBy[k], bz = sBz[k];
    int zs = bz - 8;
    int s0 = zs & 255;
    int w0 = s0 >> 5, off = s0 & 31;

    #pragma unroll
    for (int it = 0; it < 4; ++it) {
        int p = lane + it * 64;                   // 0..255, all valid
        int dx = (p >> 4) - 7;
        int dy = (p & 15) - 7;
        int cx = bx + dx, cy = by + dy;
        // (cx*SP) exact in f32 => FMA == reference fsub(fmul(cx,SP), ax)
        float rx = __fmaf_rn((float)cx, SP, -ax);
        float ry = __fmaf_rn((float)cy, SP, -ay);
        float rxy2 = __fadd_rn(__fmul_rn(rx, rx), __fmul_rn(ry, ry));
        if (rxy2 < Tocc) {                        // exact cull (s >= rxy2)
            int lo, hi;
            chord_bounds(az, rxy2, Tocc, azm, azp, lo, hi);
            if (hi >= lo) {
                unsigned mO = (2u << (hi - zs)) - (1u << (lo - zs));
                unsigned mP = 0;
                if (rxy2 < Tpro) {
                    int pl, ph;
                    chord_bounds(az, rxy2, Tpro, azm, azp, pl, ph);
                    if (ph >= pl) mP = (2u << (ph - zs)) - (1u << (pl - zs));
                }
                unsigned long long osh = ((unsigned long long)mO) << off;
                unsigned long long psh = ((unsigned long long)mP) << off;
                int colbase = ((cx & 255) << 8) | (cy & 255);
                unsigned long long v0 = ((unsigned long long)(unsigned)psh << 32)
                                      |  (unsigned long long)(unsigned)osh;
                unsigned long long v1 = ((unsigned long long)(unsigned)(psh >> 32) << 32)
                                      |  (unsigned long long)(unsigned)(osh >> 32);
                if (v0) atomicOr(&g_bits[(w0 << 16) + colbase], v0);
                if (v1) atomicOr(&g_bits[((((w0 + 1) & 7)) << 16) + colbase], v1);
            }
        }
    }
}

// ---- classify: solv = ds | (nb & ~prot); coalesced (fast index -> gy) ----
__global__ void classify_kernel() {
    __shared__ uint32_t sD0[8 * 400];
    __shared__ uint32_t sD1[8 * 400];
    __shared__ uint32_t sD2[8 * 400];
    int bx0 = (blockIdx.x & 15) * 16;
    int by0 = (blockIdx.x >> 4) * 16;
    int t = threadIdx.x;

    for (int c = t; c < 400; c += 256) {
        int iy = c % 20, ix = c / 20;              // iy fast -> gy contiguous
        int gx = (bx0 + ix - 2) & 255;
        int gy = (by0 + iy - 2) & 255;
        int col = (gx << 8) | gy;
        uint32_t ds[8], d1[8], d2[8];
        #pragma unroll
        for (int i = 0; i < 8; i++)
            ds[i] = ~(uint32_t)g_bits[(i << 16) + col];
        #pragma unroll
        for (int i = 0; i < 8; i++)
            d1[i] = ds[i] | (ds[i] << 1) | (ds[(i+7)&7] >> 31)
                          | (ds[i] >> 1) | (ds[(i+1)&7] << 31);
        #pragma unroll
        for (int i = 0; i < 8; i++)
            d2[i] = d1[i] | (d1[i] << 1) | (d1[(i+7)&7] >> 31)
                          | (d1[i] >> 1) | (d1[(i+1)&7] << 31);
        #pragma unroll
        for (int i = 0; i < 8; i++) {
            sD0[i*400 + c] = ds[i];
            sD1[i*400 + c] = d1[i];
            sD2[i*400 + c] = d2[i];
        }
    }
    __syncthreads();

    int iy = (t & 15) + 2, ix = (t >> 4) + 2;      // iy fast -> gy contiguous
    int gx = (bx0 + ix - 2) & 255;
    int gy = (by0 + iy - 2) & 255;
    int col = (gx << 8) | gy;
    int cc = ix * 20 + iy;
    #pragma unroll
    for (int i = 0; i < 8; i++) {
        const uint32_t* D0 = sD0 + i * 400;
        const uint32_t* D1 = sD1 + i * 400;
        const uint32_t* D2 = sD2 + i * 400;
        uint32_t nb =
            D2[cc] | D2[cc+1]  | D2[cc-1]  | D2[cc+20] | D2[cc-20] |
            D1[cc+21] | D1[cc+19] | D1[cc-19] | D1[cc-21] |
            D1[cc+2]  | D1[cc-2]  | D1[cc+40] | D1[cc-40] |
            D0[cc+22] | D0[cc+18] | D0[cc-18] | D0[cc-22] |
            D0[cc+41] | D0[cc+39] | D0[cc-39] | D0[cc-41];
        uint32_t p = (uint32_t)(g_bits[(i << 16) + col] >> 32);
        g_solvb[(i << 16) + col] = D0[cc] | (nb & ~p);
    }
}

// CSA of 4 one-bit vectors: sum = lo + 2*mid + 4*hi
__device__ __forceinline__ void csa4(uint32_t a, uint32_t b, uint32_t c, uint32_t d,
                                     uint32_t& lo, uint32_t& mid, uint32_t& hi) {
    uint32_t s1 = a ^ b ^ c;
    uint32_t m1 = (a & b) | (c & (a | b));
    uint32_t cy = s1 & d;
    lo  = s1 ^ d;
    mid = m1 ^ cy;
    hi  = m1 & cy;
}

// ---- fused 27-tap blur v7: per-cell 7-bit index -> 128-entry f32 LUT ----
__global__ __launch_bounds__(256)
void blur_fused7_kernel(float4* __restrict__ out,
                        float a0, float a1,
                        float p00, float p01, float p11) {
    __shared__ uint32_t sB[8][3][40];     // interior at [4+i], halos [3] and [36]
    __shared__ float    sLut[128];
    __shared__ float    sHi[8][32];
    __shared__ float    sLo[8][32];
    __shared__ float4   sOut[2048];

    int t  = threadIdx.x;
    int x  = blockIdx.x >> 3;
    int y0 = (blockIdx.x & 7) << 5;

    // re-zero splat grid for the next kernel_launch call
    g_bits[blockIdx.x * 256 + t] = 0ULL;

    if (t < 128) {
        float fE = (float)( t       & 7);
        float fC = (float)((t >> 3) & 1);
        float fK = (float)((t >> 4) & 7);
        sLut[t] = fmaf(p00, fC, fmaf(p01, fE, p11 * fK));
    }
    if (t < 192) {                         // interior: 24 (w,xi) x 8 uint4
        int combo = t >> 3;                // 0..23
        int q     = t & 7;                 // 0..7
        int w  = combo / 3;
        int xi = combo % 3;
        int gx = (x + xi - 1) & 255;
        const uint4* src = reinterpret_cast<const uint4*>(
            &g_solvb[(w << 16) | (gx << 8) | y0]);
        *reinterpret_cast<uint4*>(&sB[w][xi][4 + (q << 2)]) = src[q];
    } else if (t < 240) {                  // halos: 24 combos x 2 sides
        int e = t - 192;
        int combo = e >> 1;
        int side  = e & 1;
        int w  = combo / 3;
        int xi = combo % 3;
        int gx = (x + xi - 1) & 255;
        int gy = side ? ((y0 + 32) & 255) : ((y0 - 1) & 255);
        sB[w][xi][side ? 36 : 3] = g_solvb[(w << 16) | (gx << 8) | gy];
    }
    __syncthreads();

    int yl = t & 31;          // lane = y
    int w  = t >> 5;          // warp = word

    uint32_t cc = sB[w][1][4+yl];
    uint32_t ea = sB[w][0][4+yl], eb = sB[w][2][4+yl];
    uint32_t ec = sB[w][1][3+yl], ed = sB[w][1][5+yl];
    uint32_t ka = sB[w][0][3+yl], kb = sB[w][2][3+yl];
    uint32_t kc = sB[w][0][5+yl], kd = sB[w][2][5+yl];

    float gz[34];
    uint32_t E0, E1, E2, K0, K1, K2;
    csa4(ea, eb, ec, ed, E0, E1, E2);
    csa4(ka, kb, kc, kd, K0, K1, K2);
    #pragma unroll
    for (int G = 0; G < 4; G++) {
        uint32_t sel = (uint32_t)G | ((uint32_t)(4 + G) << 4);
        uint32_t t01 = __byte_perm(E0, E1, sel);
        uint32_t t23 = __byte_perm(E2, cc, sel);
        uint32_t t45 = __byte_perm(K0, K1, sel);
        uint32_t t67 = __byte_perm(K2, 0u, sel);
        uint32_t lo  = __byte_perm(t01, t23, 0x5410);
        uint32_t hi  = __byte_perm(t45, t67, 0x5410);
        unsigned long long xb = (unsigned long long)lo
                              | ((unsigned long long)hi << 32);
        unsigned long long yb;
        yb = (xb ^ (xb >> 7))  & 0x00AA00AA00AA00AAULL; xb ^= yb ^ (yb << 7);
        yb = (xb ^ (xb >> 14)) & 0x0000CCCC0000CCCCULL; xb ^= yb ^ (yb << 14);
        yb = (xb ^ (xb >> 28)) & 0x00000000F0F0F0F0ULL; xb ^= yb ^ (yb << 28);
        uint32_t blo = (uint32_t)xb, bhi = (uint32_t)(xb >> 32);
        float* g = &gz[1 + (G << 3)];
        g[0] = sLut[ blo        & 0xFFu];
        g[1] = sLut[(blo >>  8) & 0xFFu];
        g[2] = sLut[(blo >> 16) & 0xFFu];
        g[3] = sLut[ blo >> 24        ];
        g[4] = sLut[ bhi        & 0xFFu];
        g[5] = sLut[(bhi >>  8) & 0xFFu];
        g[6] = sLut[(bhi >> 16) & 0xFFu];
        g[7] = sLut[ bhi >> 24        ];
    }

    // word halos via smem (neighbor word lives in another warp)
    sLo[w][yl] = gz[1];
    sHi[w][yl] = gz[32];
    __syncthreads();
    gz[0]  = sHi[(w + 7) & 7][yl];
    gz[33] = sLo[(w + 1) & 7][yl];

    #pragma unroll
    for (int k = 0; k < 8; k++) {
        float4 o;
        o.x = fmaf(a0, gz[4*k+1], a1 * (gz[4*k+0] + gz[4*k+2]));
        o.y = fmaf(a0, gz[4*k+2], a1 * (gz[4*k+1] + gz[4*k+3]));
        o.z = fmaf(a0, gz[4*k+3], a1 * (gz[4*k+2] + gz[4*k+4]));
        o.w = fmaf(a0, gz[4*k+4], a1 * (gz[4*k+3] + gz[4*k+5]));
        sOut[(yl << 6) + (((w << 3) + k) ^ yl)] = o;
    }
    __syncthreads();

    #pragma unroll
    for (int k2 = 0; k2 < 8; k2++) {
        int flat = (k2 << 8) + t;
        int yy2 = flat >> 6;
        int zg2 = flat & 63;
        float4 v = sOut[(yy2 << 6) + (zg2 ^ yy2)];
        out[(x << 14) | ((y0 + yy2) << 6) | zg2] = v;
    }
}

extern "C" void kernel_launch(void* const* d_in, const int* in_sizes, int n_in,
                              void* d_out, int out_size) {
    const float* xyz = (const float*)d_in[0];
    const float* vdw = (const float*)d_in[1];
    int n_atoms = in_sizes[1];

    // all double math on the HOST; device sees only f32
    double sigma = 1.1 / (100.0 / 256.0) / 4.0;
    double w = exp(-1.0 / (2.0 * sigma * sigma));
    double s = 1.0 + 2.0 * w;
    double a0d = 1.0 / s, a1d = w / s;
    float a0  = (float)a0d;
    float a1  = (float)a1d;
    float p00 = (float)(a0d * a0d);
    float p01 = (float)(a0d * a1d);
    float p11 = (float)(a1d * a1d);

    splat_kernel      <<<(n_atoms + 3) / 4, 256>>>(xyz, vdw, n_atoms);
    classify_kernel   <<<256, 256>>>();
    blur_fused7_kernel<<<2048, 256>>>((float4*)d_out, a0, a1, p00, p01, p11);
}